// round 11
// baseline (speedup 1.0000x reference)
#include <cuda_runtime.h>

typedef unsigned long long u64;

// ---------------------------------------------------------------------------
// packed f32x2 helpers (Blackwell FFMA2 path)
// ---------------------------------------------------------------------------
__device__ __forceinline__ u64 ffma2(u64 a, u64 b, u64 c) {
    u64 d; asm("fma.rn.f32x2 %0, %1, %2, %3;" : "=l"(d) : "l"(a), "l"(b), "l"(c)); return d;
}
__device__ __forceinline__ u64 fadd2(u64 a, u64 b) {
    u64 d; asm("add.rn.f32x2 %0, %1, %2;" : "=l"(d) : "l"(a), "l"(b)); return d;
}
__device__ __forceinline__ u64 fmul2(u64 a, u64 b) {
    u64 d; asm("mul.rn.f32x2 %0, %1, %2;" : "=l"(d) : "l"(a), "l"(b)); return d;
}
__device__ __forceinline__ u64 pack2(float lo, float hi) {
    u64 d; asm("mov.b64 %0, {%1, %2};" : "=l"(d) : "f"(lo), "f"(hi)); return d;
}
__device__ __forceinline__ float2 unpk(u64 v) {
    float2 r; asm("mov.b64 {%0, %1}, %2;" : "=f"(r.x), "=f"(r.y) : "l"(v)); return r;
}
__device__ __forceinline__ u64 dup2(float c) { return pack2(c, c); }

// ---------------------------------------------------------------------------
// Tsit5 constants
// ---------------------------------------------------------------------------
#define A21f 0.161f
#define A31f (-0.008480655492356989f)
#define A32f 0.335480655492357f
#define A41f 2.8971530571054935f
#define A42f (-6.359448489975075f)
#define A43f 4.3622954328695815f
#define A51f 5.325864828439257f
#define A52f (-11.748883564062828f)
#define A53f 7.4955393428898365f
#define A54f (-0.09249506636175525f)
#define A61f 5.86145544294642f
#define A62f (-12.92096931784711f)
#define A63f 8.159367898576159f
#define A64f (-0.071584973281401f)
#define A65f (-0.028269050394068383f)
#define B1f 0.09646076681806523f
#define B2f 0.01f
#define B3f 0.4798896504144996f
#define B4f 1.379008574103742f
#define B5f (-3.290069515436081f)
#define B6f 2.324710524099774f
#define E1f (-0.00178001105222577714f)
#define E2f (-0.0008164344596567469f)
#define E3f 0.007880878010261995f
#define E4f (-0.1447110071732629f)
#define E5f 0.5823571654525552f
#define E6f (-0.45808210592918697f)
#define E7f 0.015151515151515152f

#define RTOLf 1e-3f
#define ATOLf 1e-6f
#define DT0f  1e-3f

#define DDIM 64
#define HID  32
#define TRAJ_LEN 11
#define N_INTERVALS 10
#define MAX_INNER 64

#define WARPS_PER_BLOCK 4
#define THREADS_PER_BLOCK (WARPS_PER_BLOCK * 32)
#define PERSISTENT_BLOCKS 304   // 2 blocks/SM x 152 SMs (GB300)

// global work-stealing counter (reset by init kernel every launch)
__device__ int g_sys_counter;

// fast softplus: max(x,0) + log(1 + exp(-|x|)) with MUFU exp/log
__device__ __forceinline__ float softplus_f(float x) {
    return fmaxf(x, 0.0f) + __logf(1.0f + __expf(-fabsf(x)));
}

__global__ void __launch_bounds__(THREADS_PER_BLOCK, 2)
neural_ode_kernel(const float* __restrict__ x0s,
                  const float* __restrict__ W1, const float* __restrict__ b1,
                  const float* __restrict__ W2, const float* __restrict__ b2,
                  const float* __restrict__ W3, const float* __restrict__ b3,
                  const int* __restrict__ Tptr,
                  float* __restrict__ out, int B, int nIdx)
{
    const int lane = threadIdx.x & 31;
    const int wrp  = threadIdx.x >> 5;

    const int g = lane >> 4;     // input-half group (0 or 1)
    const int m = lane & 15;     // unit-pair index: lane owns hidden units 2m, 2m+1

    // two shared buffer sets per warp (system A / system B)
    __shared__ __align__(16) float sv [WARPS_PER_BLOCK][2][DDIM];
    __shared__ __align__(16) float sh1[WARPS_PER_BLOCK][2][HID];
    __shared__ __align__(16) float sh2[WARPS_PER_BLOCK][2][HID];

    float* svA  = sv [wrp][0];  float* svB  = sv [wrp][1];
    float* h1A  = sh1[wrp][0];  float* h1B  = sh1[wrp][1];
    float* h2A  = sh2[wrp][0];  float* h2B  = sh2[wrp][1];

    // ---- weights into registers, ONCE per persistent warp (shared by A & B) ----
    u64 w1a[16], w1b[16];
    #pragma unroll
    for (int i = 0; i < 8; ++i) {
        const int c = g * 8 + ((i + g) & 7);
        float4 fa = *(const float4*)(W1 + (2 * m) * DDIM + 4 * c);
        float4 fb = *(const float4*)(W1 + (2 * m + 1) * DDIM + 4 * c);
        w1a[2 * i] = pack2(fa.x, fa.y); w1a[2 * i + 1] = pack2(fa.z, fa.w);
        w1b[2 * i] = pack2(fb.x, fb.y); w1b[2 * i + 1] = pack2(fb.z, fb.w);
    }
    u64 w2a[8], w2b[8];
    #pragma unroll
    for (int i = 0; i < 4; ++i) {
        const int c = g * 4 + i;
        float4 fa = *(const float4*)(W2 + (2 * m) * HID + 4 * c);
        float4 fb = *(const float4*)(W2 + (2 * m + 1) * HID + 4 * c);
        w2a[2 * i] = pack2(fa.x, fa.y); w2a[2 * i + 1] = pack2(fa.z, fa.w);
        w2b[2 * i] = pack2(fb.x, fb.y); w2b[2 * i + 1] = pack2(fb.z, fb.w);
    }
    u64 w3ap[HID / 2], w3bp[HID / 2];
    {
        const float2* ra = (const float2*)(W3 + (2 * lane) * HID);
        const float2* rb = (const float2*)(W3 + (2 * lane + 1) * HID);
        #pragma unroll
        for (int j = 0; j < HID / 2; ++j) {
            float2 va = ra[j]; w3ap[j] = pack2(va.x, va.y);
            float2 vb = rb[j]; w3bp[j] = pack2(vb.x, vb.y);
        }
    }
    const float2 b1v = ((const float2*)b1)[m];
    const float2 b2v = ((const float2*)b2)[m];
    const float2 b3v = ((const float2*)b3)[lane];

    const float Tf    = (float)(*Tptr);
    const float stepT = Tf / (float)N_INTERVALS;

    // dual f-eval: two systems through the MLP with interleaved chains
    auto evalf2 = [&](u64 zA, u64 zB, u64& kA, u64& kB) {
        *(u64*)&svA[2 * lane] = zA;
        *(u64*)&svB[2 * lane] = zB;
        __syncwarp();
        // ---- layer 1 (half-dot) x2 ----
        u64 A0 = 0, A1 = 0, B0 = 0, B1 = 0;      // system A, units a/b
        u64 A0b = 0, A1b = 0, B0b = 0, B1b = 0;  // system B
        const ulonglong2* vvA = (const ulonglong2*)svA;
        const ulonglong2* vvB = (const ulonglong2*)svB;
        #pragma unroll
        for (int i = 0; i < 8; ++i) {
            const int c = g * 8 + ((i + g) & 7);
            ulonglong2 pA = vvA[c];
            ulonglong2 pB = vvB[c];
            A0  = ffma2(w1a[2 * i],     pA.x, A0);
            A0b = ffma2(w1a[2 * i],     pB.x, A0b);
            A1  = ffma2(w1a[2 * i + 1], pA.y, A1);
            A1b = ffma2(w1a[2 * i + 1], pB.y, A1b);
            B0  = ffma2(w1b[2 * i],     pA.x, B0);
            B0b = ffma2(w1b[2 * i],     pB.x, B0b);
            B1  = ffma2(w1b[2 * i + 1], pA.y, B1);
            B1b = ffma2(w1b[2 * i + 1], pB.y, B1b);
        }
        float2 sa  = unpk(fadd2(A0,  A1));
        float2 sab = unpk(fadd2(A0b, A1b));
        float2 sb  = unpk(fadd2(B0,  B1));
        float2 sbb = unpk(fadd2(B0b, B1b));
        float pAa = sa.x + sa.y,  pAb = sb.x + sb.y;    // A: units 2m, 2m+1
        float pBa = sab.x + sab.y, pBb = sbb.x + sbb.y; // B
        pAa += __shfl_xor_sync(0xffffffffu, pAa, 16);
        pBa += __shfl_xor_sync(0xffffffffu, pBa, 16);
        pAb += __shfl_xor_sync(0xffffffffu, pAb, 16);
        pBb += __shfl_xor_sync(0xffffffffu, pBb, 16);
        float hAa = softplus_f(pAa + b1v.x);
        float hBa = softplus_f(pBa + b1v.x);
        float hAb = softplus_f(pAb + b1v.y);
        float hBb = softplus_f(pBb + b1v.y);
        if (lane < 16) {
            *(u64*)&h1A[2 * m] = pack2(hAa, hAb);
            *(u64*)&h1B[2 * m] = pack2(hBa, hBb);
        }
        __syncwarp();
        // ---- layer 2 (half-dot) x2 ----
        u64 C0 = 0, C1 = 0, D0 = 0, D1 = 0;
        u64 C0b = 0, C1b = 0, D0b = 0, D1b = 0;
        const ulonglong2* hhA = (const ulonglong2*)h1A;
        const ulonglong2* hhB = (const ulonglong2*)h1B;
        #pragma unroll
        for (int i = 0; i < 4; ++i) {
            ulonglong2 pA = hhA[g * 4 + i];
            ulonglong2 pB = hhB[g * 4 + i];
            C0  = ffma2(w2a[2 * i],     pA.x, C0);
            C0b = ffma2(w2a[2 * i],     pB.x, C0b);
            C1  = ffma2(w2a[2 * i + 1], pA.y, C1);
            C1b = ffma2(w2a[2 * i + 1], pB.y, C1b);
            D0  = ffma2(w2b[2 * i],     pA.x, D0);
            D0b = ffma2(w2b[2 * i],     pB.x, D0b);
            D1  = ffma2(w2b[2 * i + 1], pA.y, D1);
            D1b = ffma2(w2b[2 * i + 1], pB.y, D1b);
        }
        float2 sc  = unpk(fadd2(C0,  C1));
        float2 scb = unpk(fadd2(C0b, C1b));
        float2 sd  = unpk(fadd2(D0,  D1));
        float2 sdb = unpk(fadd2(D0b, D1b));
        float qAa = sc.x + sc.y,  qAb = sd.x + sd.y;
        float qBa = scb.x + scb.y, qBb = sdb.x + sdb.y;
        qAa += __shfl_xor_sync(0xffffffffu, qAa, 16);
        qBa += __shfl_xor_sync(0xffffffffu, qBa, 16);
        qAb += __shfl_xor_sync(0xffffffffu, qAb, 16);
        qBb += __shfl_xor_sync(0xffffffffu, qBb, 16);
        float gAa = softplus_f(qAa + b2v.x);
        float gBa = softplus_f(qBa + b2v.x);
        float gAb = softplus_f(qAb + b2v.y);
        float gBb = softplus_f(qBb + b2v.y);
        if (lane < 16) {
            *(u64*)&h2A[2 * m] = pack2(gAa, gAb);
            *(u64*)&h2B[2 * m] = pack2(gBa, gBb);
        }
        __syncwarp();
        // ---- layer 3 (full dot) x2 ----
        u64 e0 = 0, e1 = 0, f0 = 0, f1 = 0;      // A: rows 2*lane / 2*lane+1
        u64 e0b = 0, e1b = 0, f0b = 0, f1b = 0;  // B
        const ulonglong2* ggA = (const ulonglong2*)h2A;
        const ulonglong2* ggB = (const ulonglong2*)h2B;
        #pragma unroll
        for (int j = 0; j < 4; ++j) {
            ulonglong2 pA0 = ggA[2 * j + 0];
            ulonglong2 pA1 = ggA[2 * j + 1];
            ulonglong2 pB0 = ggB[2 * j + 0];
            ulonglong2 pB1 = ggB[2 * j + 1];
            e0  = ffma2(w3ap[4 * j + 0], pA0.x, e0);
            e0b = ffma2(w3ap[4 * j + 0], pB0.x, e0b);
            f0  = ffma2(w3bp[4 * j + 0], pA0.x, f0);
            f0b = ffma2(w3bp[4 * j + 0], pB0.x, f0b);
            e1  = ffma2(w3ap[4 * j + 1], pA0.y, e1);
            e1b = ffma2(w3ap[4 * j + 1], pB0.y, e1b);
            f1  = ffma2(w3bp[4 * j + 1], pA0.y, f1);
            f1b = ffma2(w3bp[4 * j + 1], pB0.y, f1b);
            e0  = ffma2(w3ap[4 * j + 2], pA1.x, e0);
            e0b = ffma2(w3ap[4 * j + 2], pB1.x, e0b);
            f0  = ffma2(w3bp[4 * j + 2], pA1.x, f0);
            f0b = ffma2(w3bp[4 * j + 2], pB1.x, f0b);
            e1  = ffma2(w3ap[4 * j + 3], pA1.y, e1);
            e1b = ffma2(w3ap[4 * j + 3], pB1.y, e1b);
            f1  = ffma2(w3bp[4 * j + 3], pA1.y, f1);
            f1b = ffma2(w3bp[4 * j + 3], pB1.y, f1b);
        }
        float2 se  = unpk(fadd2(e0,  e1));
        float2 seb = unpk(fadd2(e0b, e1b));
        float2 sf  = unpk(fadd2(f0,  f1));
        float2 sfb = unpk(fadd2(f0b, f1b));
        kA = pack2((se.x + se.y) + b3v.x, (sf.x + sf.y) + b3v.y);
        kB = pack2((seb.x + seb.y) + b3v.x, (sfb.x + sfb.y) + b3v.y);
        // no trailing syncwarp: next call's barriers cover the WAR hazards
    };

    // =======================================================================
    // persistent loop: steal PAIRS of systems
    // =======================================================================
    const int nPairs = (B + 1) >> 1;
    for (;;) {
        int pair;
        if (lane == 0) pair = atomicAdd(&g_sys_counter, 1);
        pair = __shfl_sync(0xffffffffu, pair, 0);
        if (pair >= nPairs) break;

        const int sysA = 2 * pair;
        const int sysB = 2 * pair + 1;
        const bool haveB = (sysB < B);

        float2 xA = ((const float2*)x0s)[sysA * (DDIM / 2) + lane];
        float2 xB = haveB ? ((const float2*)x0s)[sysB * (DDIM / 2) + lane] : xA;
        u64 yA = pack2(xA.x, xA.y);
        u64 yB = pack2(xB.x, xB.y);

        const int baseA = sysA * (TRAJ_LEN * DDIM);
        const int baseB = sysB * (TRAJ_LEN * DDIM);
        ((float2*)out)[(baseA >> 1) + lane] = xA;
        if (haveB) ((float2*)out)[(baseB >> 1) + lane] = xB;

        float tA = 0.0f, tB = 0.0f;
        float dtA = DT0f, dtB = DT0f;
        int   nA = 0, nB = 0;

        u64 k1A, k1B;
        evalf2(yA, yB, k1A, k1B);   // FSAL seeds

        for (int iv = 1; iv <= N_INTERVALS; ++iv) {
            const float t_target = (iv == N_INTERVALS) ? Tf : stepT * (float)iv;

            for (int it = 0; it < MAX_INNER; ++it) {
                float remA = t_target - tA;
                float remB = t_target - tB;
                bool doneA = (remA <= 1e-12f);
                bool doneB = (remB <= 1e-12f);
                if (doneA && doneB) break;

                float hA = fminf(dtA, fmaxf(remA, 0.0f));
                float hB = fminf(dtB, fmaxf(remB, 0.0f));
                u64 hpA = dup2(hA);
                u64 hpB = dup2(hB);

                u64 k2A, k2B, k3A, k3B, k4A, k4B, k5A, k5B, k6A, k6B, k7A, k7B;
                u64 sA, sB;

                // stage 2
                sA = fmul2(dup2(A21f), k1A);
                sB = fmul2(dup2(A21f), k1B);
                evalf2(ffma2(hpA, sA, yA), ffma2(hpB, sB, yB), k2A, k2B);
                // stage 3
                sA = ffma2(dup2(A32f), k2A, fmul2(dup2(A31f), k1A));
                sB = ffma2(dup2(A32f), k2B, fmul2(dup2(A31f), k1B));
                evalf2(ffma2(hpA, sA, yA), ffma2(hpB, sB, yB), k3A, k3B);
                // stage 4
                sA = ffma2(dup2(A42f), k2A, fmul2(dup2(A41f), k1A));
                sB = ffma2(dup2(A42f), k2B, fmul2(dup2(A41f), k1B));
                sA = ffma2(dup2(A43f), k3A, sA);
                sB = ffma2(dup2(A43f), k3B, sB);
                evalf2(ffma2(hpA, sA, yA), ffma2(hpB, sB, yB), k4A, k4B);
                // stage 5
                sA = ffma2(dup2(A52f), k2A, fmul2(dup2(A51f), k1A));
                sB = ffma2(dup2(A52f), k2B, fmul2(dup2(A51f), k1B));
                sA = ffma2(dup2(A53f), k3A, sA);
                sB = ffma2(dup2(A53f), k3B, sB);
                sA = ffma2(dup2(A54f), k4A, sA);
                sB = ffma2(dup2(A54f), k4B, sB);
                evalf2(ffma2(hpA, sA, yA), ffma2(hpB, sB, yB), k5A, k5B);
                // stage 6
                sA = ffma2(dup2(A62f), k2A, fmul2(dup2(A61f), k1A));
                sB = ffma2(dup2(A62f), k2B, fmul2(dup2(A61f), k1B));
                sA = ffma2(dup2(A63f), k3A, sA);
                sB = ffma2(dup2(A63f), k3B, sB);
                sA = ffma2(dup2(A64f), k4A, sA);
                sB = ffma2(dup2(A64f), k4B, sB);
                sA = ffma2(dup2(A65f), k5A, sA);
                sB = ffma2(dup2(A65f), k5B, sB);
                evalf2(ffma2(hpA, sA, yA), ffma2(hpB, sB, yB), k6A, k6B);
                // y5
                sA = ffma2(dup2(B2f), k2A, fmul2(dup2(B1f), k1A));
                sB = ffma2(dup2(B2f), k2B, fmul2(dup2(B1f), k1B));
                sA = ffma2(dup2(B3f), k3A, sA);
                sB = ffma2(dup2(B3f), k3B, sB);
                sA = ffma2(dup2(B4f), k4A, sA);
                sB = ffma2(dup2(B4f), k4B, sB);
                sA = ffma2(dup2(B5f), k5A, sA);
                sB = ffma2(dup2(B5f), k5B, sB);
                sA = ffma2(dup2(B6f), k6A, sA);
                sB = ffma2(dup2(B6f), k6B, sB);
                u64 y5A = ffma2(hpA, sA, yA);
                u64 y5B = ffma2(hpB, sB, yB);
                // stage 7 (FSAL)
                evalf2(y5A, y5B, k7A, k7B);
                // error estimate
                sA = ffma2(dup2(E2f), k2A, fmul2(dup2(E1f), k1A));
                sB = ffma2(dup2(E2f), k2B, fmul2(dup2(E1f), k1B));
                sA = ffma2(dup2(E3f), k3A, sA);
                sB = ffma2(dup2(E3f), k3B, sB);
                sA = ffma2(dup2(E4f), k4A, sA);
                sB = ffma2(dup2(E4f), k4B, sB);
                sA = ffma2(dup2(E5f), k5A, sA);
                sB = ffma2(dup2(E5f), k5B, sB);
                sA = ffma2(dup2(E6f), k6A, sA);
                sB = ffma2(dup2(E6f), k6B, sB);
                sA = ffma2(dup2(E7f), k7A, sA);
                sB = ffma2(dup2(E7f), k7B, sB);
                float2 evA = unpk(fmul2(hpA, sA));
                float2 evB = unpk(fmul2(hpB, sB));
                float2 yvA = unpk(yA);
                float2 yvB = unpk(yB);
                float2 y5vA = unpk(y5A);
                float2 y5vB = unpk(y5B);

                float sclA = fmaf(RTOLf, fmaxf(fabsf(yvA.x), fabsf(y5vA.x)), ATOLf);
                float schA = fmaf(RTOLf, fmaxf(fabsf(yvA.y), fabsf(y5vA.y)), ATOLf);
                float sclB = fmaf(RTOLf, fmaxf(fabsf(yvB.x), fabsf(y5vB.x)), ATOLf);
                float schB = fmaf(RTOLf, fmaxf(fabsf(yvB.y), fabsf(y5vB.y)), ATOLf);
                float qlA = __fdividef(evA.x, sclA);
                float qhA = __fdividef(evA.y, schA);
                float qlB = __fdividef(evB.x, sclB);
                float qhB = __fdividef(evB.y, schB);
                float locA = qlA * qlA + qhA * qhA;
                float locB = qlB * qlB + qhB * qhB;
                #pragma unroll
                for (int o = 16; o > 0; o >>= 1) {
                    locA += __shfl_xor_sync(0xffffffffu, locA, o);
                    locB += __shfl_xor_sync(0xffffffffu, locB, o);
                }

                // accept <=> local <= 64; fac = 0.9*exp2(-0.1*(log2(local)-6))
                bool accA = (locA <= 64.0f);
                bool accB = (locB <= 64.0f);
                float lgA = __log2f(fmaxf(locA, 4.096e-18f)) - 6.0f;
                float lgB = __log2f(fmaxf(locB, 4.096e-18f)) - 6.0f;
                float facA = fminf(fmaxf(0.9f * exp2f(-0.1f * lgA), 0.1f), 5.0f);
                float facB = fminf(fmaxf(0.9f * exp2f(-0.1f * lgB), 0.1f), 5.0f);

                if (!doneA) {
                    if (accA) { tA += hA; yA = y5A; k1A = k7A; }
                    dtA = fmaxf(hA * facA, 1e-8f);
                    nA += 1;
                }
                if (!doneB) {
                    if (accB) { tB += hB; yB = y5B; k1B = k7B; }
                    dtB = fmaxf(hB * facB, 1e-8f);
                    nB += 1;
                }
            }

            float2 yvA = unpk(yA);
            ((float2*)out)[((baseA + iv * DDIM) >> 1) + lane] = yvA;
            if (haveB) {
                float2 yvB = unpk(yB);
                ((float2*)out)[((baseB + iv * DDIM) >> 1) + lane] = yvB;
            }
        }

        if (lane == 0) {
            float nsum = (float)nA + (haveB ? (float)nB : 0.0f);
            atomicAdd(&out[nIdx], nsum);   // integer-valued, exact
        }
    }
}

// zero the poisoned tail of the output buffer AND the work-stealing counter
__global__ void init_kernel(float* __restrict__ out, int start, int total) {
    if (blockIdx.x == 0 && threadIdx.x == 0) g_sys_counter = 0;
    int i = start + blockIdx.x * blockDim.x + threadIdx.x;
    if (i < total) out[i] = 0.0f;
}

extern "C" void kernel_launch(void* const* d_in, const int* in_sizes, int n_in,
                              void* d_out, int out_size) {
    const float* x0s = (const float*)d_in[0];
    const float* W1  = (const float*)d_in[1];
    const float* b1  = (const float*)d_in[2];
    const float* W2  = (const float*)d_in[3];
    const float* b2  = (const float*)d_in[4];
    const float* W3  = (const float*)d_in[5];
    const float* b3  = (const float*)d_in[6];
    const int*   Tp  = (const int*)d_in[7];

    const int B = in_sizes[0] / DDIM;
    float* out = (float*)d_out;

    int trajElems = B * TRAJ_LEN * DDIM;
    if (trajElems >= out_size) trajElems = out_size - 1;  // safety
    const int nIdx = trajElems;

    const int tail = out_size - trajElems;
    int initBlocks = (tail + 255) / 256; if (initBlocks < 1) initBlocks = 1;
    init_kernel<<<initBlocks, 256>>>(out, trajElems, out_size);

    neural_ode_kernel<<<PERSISTENT_BLOCKS, THREADS_PER_BLOCK>>>(
        x0s, W1, b1, W2, b2, W3, b3, Tp, out, B, nIdx);
}

// round 12
// speedup vs baseline: 1.0467x; 1.0467x over previous
#include <cuda_runtime.h>

typedef unsigned long long u64;

// ---------------------------------------------------------------------------
// packed f32x2 helpers (Blackwell FFMA2 path)
// ---------------------------------------------------------------------------
__device__ __forceinline__ u64 ffma2(u64 a, u64 b, u64 c) {
    u64 d; asm("fma.rn.f32x2 %0, %1, %2, %3;" : "=l"(d) : "l"(a), "l"(b), "l"(c)); return d;
}
__device__ __forceinline__ u64 fadd2(u64 a, u64 b) {
    u64 d; asm("add.rn.f32x2 %0, %1, %2;" : "=l"(d) : "l"(a), "l"(b)); return d;
}
__device__ __forceinline__ u64 fmul2(u64 a, u64 b) {
    u64 d; asm("mul.rn.f32x2 %0, %1, %2;" : "=l"(d) : "l"(a), "l"(b)); return d;
}
__device__ __forceinline__ u64 pack2(float lo, float hi) {
    u64 d; asm("mov.b64 %0, {%1, %2};" : "=l"(d) : "f"(lo), "f"(hi)); return d;
}
__device__ __forceinline__ float2 unpk(u64 v) {
    float2 r; asm("mov.b64 {%0, %1}, %2;" : "=f"(r.x), "=f"(r.y) : "l"(v)); return r;
}
__device__ __forceinline__ u64 dup2(float c) { return pack2(c, c); }

// ---------------------------------------------------------------------------
// Tsit5 constants
// ---------------------------------------------------------------------------
#define A21f 0.161f
#define A31f (-0.008480655492356989f)
#define A32f 0.335480655492357f
#define A41f 2.8971530571054935f
#define A42f (-6.359448489975075f)
#define A43f 4.3622954328695815f
#define A51f 5.325864828439257f
#define A52f (-11.748883564062828f)
#define A53f 7.4955393428898365f
#define A54f (-0.09249506636175525f)
#define A61f 5.86145544294642f
#define A62f (-12.92096931784711f)
#define A63f 8.159367898576159f
#define A64f (-0.071584973281401f)
#define A65f (-0.028269050394068383f)
#define B1f 0.09646076681806523f
#define B2f 0.01f
#define B3f 0.4798896504144996f
#define B4f 1.379008574103742f
#define B5f (-3.290069515436081f)
#define B6f 2.324710524099774f
#define E1f (-0.00178001105222577714f)
#define E2f (-0.0008164344596567469f)
#define E3f 0.007880878010261995f
#define E4f (-0.1447110071732629f)
#define E5f 0.5823571654525552f
#define E6f (-0.45808210592918697f)
#define E7f 0.015151515151515152f

#define RTOLf 1e-3f
#define ATOLf 1e-6f
#define DT0f  1e-3f

#define DDIM 64
#define HID  32
#define TRAJ_LEN 11
#define N_INTERVALS 10
#define MAX_INNER 64

#define WARPS_PER_BLOCK 4
#define THREADS_PER_BLOCK (WARPS_PER_BLOCK * 32)
#define PERSISTENT_BLOCKS 304   // 2 blocks/SM x 152 SMs (GB300)

// global work-stealing counter (reset by init kernel every launch)
__device__ int g_sys_counter;

// fast softplus: max(x,0) + log(1 + exp(-|x|)) with MUFU exp/log
__device__ __forceinline__ float softplus_f(float x) {
    return fmaxf(x, 0.0f) + __logf(1.0f + __expf(-fabsf(x)));
}

__global__ void __launch_bounds__(THREADS_PER_BLOCK, 2)
neural_ode_kernel(const float* __restrict__ x0s,
                  const float* __restrict__ W1, const float* __restrict__ b1,
                  const float* __restrict__ W2, const float* __restrict__ b2,
                  const float* __restrict__ W3, const float* __restrict__ b3,
                  const int* __restrict__ Tptr,
                  float* __restrict__ out, int B, int nIdx)
{
    const int lane = threadIdx.x & 31;
    const int wrp  = threadIdx.x >> 5;

    const int q  = lane >> 3;    // input quarter (0..3) for L1
    const int mq = lane & 7;     // L1 unit base: units {mq, mq+8, mq+16, mq+24}
    const int g  = lane >> 4;    // input half (0/1) for L2/L3
    const int m16 = lane & 15;   // L2 units {m16, m16+16}; L3 rows {m16+16j}

    __shared__ __align__(16) float sv [WARPS_PER_BLOCK][DDIM]; // stage vector z
    __shared__ __align__(16) float sh1[WARPS_PER_BLOCK][HID];  // hidden 1
    __shared__ __align__(16) float sh2[WARPS_PER_BLOCK][HID];  // hidden 2

    float* svw  = sv [wrp];
    float* sh1w = sh1[wrp];
    float* sh2w = sh2[wrp];

    // ---- weights into registers, ONCE per persistent warp ----
    // L1: 4 units x quarter-input (16 floats) = 32 u64
    u64 w1q[32];
    #pragma unroll
    for (int j = 0; j < 4; ++j) {
        const int u = mq + 8 * j;
        const float2* r = (const float2*)(W1 + u * DDIM + 16 * q);
        #pragma unroll
        for (int k = 0; k < 8; ++k) { float2 v = r[k]; w1q[j * 8 + k] = pack2(v.x, v.y); }
    }
    // L2: 2 units x half-input (16 floats) = 16 u64
    u64 w2u[16];
    #pragma unroll
    for (int j = 0; j < 2; ++j) {
        const int u = m16 + 16 * j;
        const float2* r = (const float2*)(W2 + u * HID + 16 * g);
        #pragma unroll
        for (int k = 0; k < 8; ++k) { float2 v = r[k]; w2u[j * 8 + k] = pack2(v.x, v.y); }
    }
    // L3: 4 rows {m16+16j} x half-input (16 floats) = 32 u64
    u64 w3r[32];
    #pragma unroll
    for (int j = 0; j < 4; ++j) {
        const int row = m16 + 16 * j;
        const float2* r = (const float2*)(W3 + row * HID + 16 * g);
        #pragma unroll
        for (int k = 0; k < 8; ++k) { float2 v = r[k]; w3r[j * 8 + k] = pack2(v.x, v.y); }
    }
    const float b1r = b1[lane];
    const float b2r = b2[lane];
    const u64 b3p = pack2(b3[lane], b3[lane + 32]);

    const float Tf    = (float)(*Tptr);
    const float stepT = Tf / (float)N_INTERVALS;

    // f(z) -> k; z/k packed as coords (lane, lane+32)
    auto evalf = [&](u64 z) -> u64 {
        float2 zz = unpk(z);
        svw[lane]      = zz.x;    // STS.32
        svw[lane + 32] = zz.y;    // STS.32
        __syncwarp();
        // ---- L1 quarter-split: 4 LDS.128, 32 FFMA2, 2 shfl rounds ----
        u64 a0 = 0, a1 = 0, a2 = 0, a3 = 0;
        const ulonglong2* vv = (const ulonglong2*)svw;
        #pragma unroll
        for (int c = 0; c < 4; ++c) {
            ulonglong2 ch = vv[4 * q + c];
            a0 = ffma2(w1q[2 * c],      ch.x, a0);
            a1 = ffma2(w1q[8 + 2 * c],  ch.x, a1);
            a2 = ffma2(w1q[16 + 2 * c], ch.x, a2);
            a3 = ffma2(w1q[24 + 2 * c], ch.x, a3);
            a0 = ffma2(w1q[2 * c + 1],      ch.y, a0);
            a1 = ffma2(w1q[8 + 2 * c + 1],  ch.y, a1);
            a2 = ffma2(w1q[16 + 2 * c + 1], ch.y, a2);
            a3 = ffma2(w1q[24 + 2 * c + 1], ch.y, a3);
        }
        float2 f0 = unpk(a0), f1 = unpk(a1), f2 = unpk(a2), f3 = unpk(a3);
        u64 P = pack2(f0.x + f0.y, f1.x + f1.y);   // units (mq, mq+8)
        u64 Q = pack2(f2.x + f2.y, f3.x + f3.y);   // units (mq+16, mq+24)
        P = fadd2(P, __shfl_xor_sync(0xffffffffu, P, 8));
        Q = fadd2(Q, __shfl_xor_sync(0xffffffffu, Q, 8));
        P = fadd2(P, __shfl_xor_sync(0xffffffffu, P, 16));
        Q = fadd2(Q, __shfl_xor_sync(0xffffffffu, Q, 16));
        float2 Pv = unpk(P), Qv = unpk(Q);
        // unit this lane stores: mq + 8*q == lane
        float pre1 = (q == 0) ? Pv.x : (q == 1) ? Pv.y : (q == 2) ? Qv.x : Qv.y;
        sh1w[lane] = softplus_f(pre1 + b1r);   // STS.32 to h1[lane]
        __syncwarp();
        // ---- L2 half-split: 4 LDS.128, 16 FFMA2, 1 shfl round ----
        u64 cA = 0, cB = 0;
        const ulonglong2* hh = (const ulonglong2*)sh1w;
        #pragma unroll
        for (int c = 0; c < 4; ++c) {
            ulonglong2 ch = hh[4 * g + c];
            cA = ffma2(w2u[2 * c],     ch.x, cA);
            cB = ffma2(w2u[8 + 2 * c], ch.x, cB);
            cA = ffma2(w2u[2 * c + 1],     ch.y, cA);
            cB = ffma2(w2u[8 + 2 * c + 1], ch.y, cB);
        }
        float2 fa = unpk(cA), fb = unpk(cB);
        u64 R = pack2(fa.x + fa.y, fb.x + fb.y);   // units (m16, m16+16)
        R = fadd2(R, __shfl_xor_sync(0xffffffffu, R, 16));
        float2 Rv = unpk(R);
        float pre2 = (g == 0) ? Rv.x : Rv.y;       // unit m16+16g == lane
        sh2w[lane] = softplus_f(pre2 + b2r);       // STS.32 to h2[lane]
        __syncwarp();
        // ---- L3 half-split: 4 LDS.128, 32 FFMA2, 1 shfl round, free placement ----
        u64 e0 = 0, e1 = 0, e2 = 0, e3 = 0;  // rows m16, m16+16, m16+32, m16+48
        const ulonglong2* gg = (const ulonglong2*)sh2w;
        #pragma unroll
        for (int c = 0; c < 4; ++c) {
            ulonglong2 ch = gg[4 * g + c];
            e0 = ffma2(w3r[2 * c],      ch.x, e0);
            e1 = ffma2(w3r[8 + 2 * c],  ch.x, e1);
            e2 = ffma2(w3r[16 + 2 * c], ch.x, e2);
            e3 = ffma2(w3r[24 + 2 * c], ch.x, e3);
            e0 = ffma2(w3r[2 * c + 1],      ch.y, e0);
            e1 = ffma2(w3r[8 + 2 * c + 1],  ch.y, e1);
            e2 = ffma2(w3r[16 + 2 * c + 1], ch.y, e2);
            e3 = ffma2(w3r[24 + 2 * c + 1], ch.y, e3);
        }
        float2 s0 = unpk(e0), s1 = unpk(e1), s2 = unpk(e2), s3 = unpk(e3);
        u64 P3 = pack2(s0.x + s0.y, s2.x + s2.y);  // rows (m16, m16+32)
        u64 Q3 = pack2(s1.x + s1.y, s3.x + s3.y);  // rows (m16+16, m16+48)
        P3 = fadd2(P3, __shfl_xor_sync(0xffffffffu, P3, 16));
        Q3 = fadd2(Q3, __shfl_xor_sync(0xffffffffu, Q3, 16));
        // lane needs rows (lane, lane+32): g==0 -> P3, g==1 -> Q3. no traffic.
        u64 kv = (g == 0) ? P3 : Q3;
        // no trailing syncwarp: next call's barriers cover the WAR hazards
        return fadd2(kv, b3p);
    };

    // =======================================================================
    // persistent loop: steal system IDs until exhausted
    // =======================================================================
    for (;;) {
        int sys;
        if (lane == 0) sys = atomicAdd(&g_sys_counter, 1);
        sys = __shfl_sync(0xffffffffu, sys, 0);
        if (sys >= B) break;

        // state: coords (lane, lane+32)
        float ylo = x0s[sys * DDIM + lane];
        float yhi = x0s[sys * DDIM + 32 + lane];
        u64 yp = pack2(ylo, yhi);

        const int trajBase = sys * (TRAJ_LEN * DDIM);
        out[trajBase + lane]      = ylo;   // ts[0] row
        out[trajBase + 32 + lane] = yhi;

        float t = 0.0f;
        float dt = DT0f;
        int   n  = 0;

        u64 k1p = evalf(yp);   // FSAL seed

        for (int iv = 1; iv <= N_INTERVALS; ++iv) {
            const float t_target = (iv == N_INTERVALS) ? Tf : stepT * (float)iv;

            for (int it = 0; it < MAX_INNER; ++it) {
                float remaining = t_target - t;
                if (remaining <= 1e-12f) break;
                float h = fminf(dt, fmaxf(remaining, 0.0f));
                u64 hp = dup2(h);

                // stage 2
                u64 s = fmul2(dup2(A21f), k1p);
                u64 k2p = evalf(ffma2(hp, s, yp));
                // stage 3
                s = ffma2(dup2(A32f), k2p, fmul2(dup2(A31f), k1p));
                u64 k3p = evalf(ffma2(hp, s, yp));
                // stage 4
                s = ffma2(dup2(A42f), k2p, fmul2(dup2(A41f), k1p));
                s = ffma2(dup2(A43f), k3p, s);
                u64 k4p = evalf(ffma2(hp, s, yp));
                // stage 5
                s = ffma2(dup2(A52f), k2p, fmul2(dup2(A51f), k1p));
                s = ffma2(dup2(A53f), k3p, s);
                s = ffma2(dup2(A54f), k4p, s);
                u64 k5p = evalf(ffma2(hp, s, yp));
                // stage 6
                s = ffma2(dup2(A62f), k2p, fmul2(dup2(A61f), k1p));
                s = ffma2(dup2(A63f), k3p, s);
                s = ffma2(dup2(A64f), k4p, s);
                s = ffma2(dup2(A65f), k5p, s);
                u64 k6p = evalf(ffma2(hp, s, yp));
                // y5
                s = ffma2(dup2(B2f), k2p, fmul2(dup2(B1f), k1p));
                s = ffma2(dup2(B3f), k3p, s);
                s = ffma2(dup2(B4f), k4p, s);
                s = ffma2(dup2(B5f), k5p, s);
                s = ffma2(dup2(B6f), k6p, s);
                u64 y5p = ffma2(hp, s, yp);
                // stage 7 (FSAL)
                u64 k7p = evalf(y5p);
                // error estimate
                s = ffma2(dup2(E2f), k2p, fmul2(dup2(E1f), k1p));
                s = ffma2(dup2(E3f), k3p, s);
                s = ffma2(dup2(E4f), k4p, s);
                s = ffma2(dup2(E5f), k5p, s);
                s = ffma2(dup2(E6f), k6p, s);
                s = ffma2(dup2(E7f), k7p, s);
                float2 ev  = unpk(fmul2(hp, s));
                float2 yv  = unpk(yp);
                float2 y5v = unpk(y5p);

                float scl = fmaf(RTOLf, fmaxf(fabsf(yv.x), fabsf(y5v.x)), ATOLf);
                float sch = fmaf(RTOLf, fmaxf(fabsf(yv.y), fabsf(y5v.y)), ATOLf);
                float ql = __fdividef(ev.x, scl);
                float qh = __fdividef(ev.y, sch);
                float local = ql * ql + qh * qh;
                #pragma unroll
                for (int o = 16; o > 0; o >>= 1)
                    local += __shfl_xor_sync(0xffffffffu, local, o);

                // accept <=> local <= 64; fac = 0.9*exp2(-0.1*(log2(local)-6))
                bool accept = (local <= 64.0f);
                float lg = __log2f(fmaxf(local, 4.096e-18f)) - 6.0f;
                float fac = 0.9f * exp2f(-0.1f * lg);
                fac = fminf(fmaxf(fac, 0.1f), 5.0f);

                if (accept) {
                    t = t + h;
                    yp  = y5p;
                    k1p = k7p;   // FSAL
                }
                dt = fmaxf(h * fac, 1e-8f);
                n += 1;
            }

            float2 yv = unpk(yp);
            out[trajBase + iv * DDIM + lane]      = yv.x;
            out[trajBase + iv * DDIM + 32 + lane] = yv.y;
        }

        if (lane == 0)
            atomicAdd(&out[nIdx], (float)n);   // integer-valued, exact
    }
}

// zero the poisoned tail of the output buffer AND the work-stealing counter
__global__ void init_kernel(float* __restrict__ out, int start, int total) {
    if (blockIdx.x == 0 && threadIdx.x == 0) g_sys_counter = 0;
    int i = start + blockIdx.x * blockDim.x + threadIdx.x;
    if (i < total) out[i] = 0.0f;
}

extern "C" void kernel_launch(void* const* d_in, const int* in_sizes, int n_in,
                              void* d_out, int out_size) {
    const float* x0s = (const float*)d_in[0];
    const float* W1  = (const float*)d_in[1];
    const float* b1  = (const float*)d_in[2];
    const float* W2  = (const float*)d_in[3];
    const float* b2  = (const float*)d_in[4];
    const float* W3  = (const float*)d_in[5];
    const float* b3  = (const float*)d_in[6];
    const int*   Tp  = (const int*)d_in[7];

    const int B = in_sizes[0] / DDIM;
    float* out = (float*)d_out;

    int trajElems = B * TRAJ_LEN * DDIM;
    if (trajElems >= out_size) trajElems = out_size - 1;  // safety
    const int nIdx = trajElems;

    const int tail = out_size - trajElems;
    int initBlocks = (tail + 255) / 256; if (initBlocks < 1) initBlocks = 1;
    init_kernel<<<initBlocks, 256>>>(out, trajElems, out_size);

    neural_ode_kernel<<<PERSISTENT_BLOCKS, THREADS_PER_BLOCK>>>(
        x0s, W1, b1, W2, b2, W3, b3, Tp, out, B, nIdx);
}